// round 7
// baseline (speedup 1.0000x reference)
#include <cuda_runtime.h>
#include <cstdint>
#include <cstddef>

// Depthwise conv1d: B=8, L=16384, C=512, K=31, SAME, fp32.
// Parity-split streaming stencil: warp-pair shares one cp.async SMEM slab
// stream (each warp loads 8 of 16 rows); warp P in {0,1} computes outputs o
// with (o-l0)%2==P via a 16-slot f32x2 ring (~110 regs -> 16 warps/SM).
// Stream step s = 0..94, input q = l0-16+s contributes w[k] to o = l0-1+s-k;
// warp P's taps each step: k === s-1-P (mod 2). slot(o) = ((o-l0-P)/2) & 15.
// Output o completes on its k=30 tap at s = o-l0+31.
// Sync: cp.async.wait_group + __syncthreads (canonical publish pattern).

constexpr int B_   = 8;
constexpr int L_   = 16384;
constexpr int C_   = 512;
constexpr int K_   = 31;
constexpr int RCH  = 64;           // L outputs per block
constexpr int TPB  = 256;          // 8 warps = 4 groups x 2 parities
constexpr int CW   = C_ / 2;       // 256 u64 per L-row
constexpr int ROWB = 2048;         // bytes per full L-row (512 floats)
constexpr int NSLAB = 6;           // 96 stream rows (need 95)

using u64 = unsigned long long;

__device__ __forceinline__ u64 ffma2(u64 a, u64 b, u64 c) {
    u64 d;
    asm("fma.rn.f32x2 %0, %1, %2, %3;" : "=l"(d) : "l"(a), "l"(b), "l"(c));
    return d;
}
__device__ __forceinline__ void stg_cs(u64* p, u64 v) {
    asm volatile("st.global.cs.b64 [%0], %1;" :: "l"(p), "l"(v));
}
__device__ __forceinline__ void cpa16(unsigned saddr, const void* gptr, unsigned sz) {
    asm volatile("cp.async.cg.shared.global [%0], [%1], 16, %2;\n"
                 :: "r"(saddr), "l"(gptr), "r"(sz));
}
__device__ __forceinline__ void cpcommit() { asm volatile("cp.async.commit_group;\n"); }
template <int N>
__device__ __forceinline__ void cpwait() { asm volatile("cp.async.wait_group %0;\n" :: "n"(N)); }

struct Copier {
    const char* xgo;    // x + batch + group channel base + in-row byte offset
    unsigned    sdst0;  // smem group buf0 base + row/byte offset for this thread
    int         q00;    // l0 - 16 + first row this thread serves

    // Each warp of the pair loads its 8 rows (2 KB) of the 4 KB group slab.
    // OOB rows (SAME padding) zero-filled via src_size = 0.
    __device__ __forceinline__ void issue(int slab, int buf) const {
        if (slab >= NSLAB) { cpcommit(); return; }   // uniform group count
        const int q = q00 + slab * 16;
#pragma unroll
        for (int c = 0; c < 4; ++c) {
            int qq = q + 2 * c;
            int qc = qq < 0 ? 0 : (qq >= L_ ? L_ - 1 : qq);
            unsigned sz = (qq >= 0 && qq < L_) ? 16u : 0u;
            cpa16(sdst0 + (unsigned)buf * 4096 + (unsigned)c * 512,
                  xgo + (long)qc * ROWB, sz);
        }
        cpcommit();
    }
};

// Ramp slab (SB in {0,16}): taps clipped to k <= s-1 (outputs o >= l0 only).
// Single ramp store: o = l0 at s = 31 (parity P = 0).
template <int SB, int P>
__device__ __forceinline__ void ramp_slab(const u64* __restrict__ sl, int lane,
                                          const u64* __restrict__ wr,
                                          u64* __restrict__ acc, u64 bb,
                                          u64*& op)
{
#pragma unroll
    for (int u = 0; u < 16; ++u) {
        const int s = SB + u;
        const u64 v = sl[u * 32 + lane];
        const int kpar = (s + 1 + P) & 1;            // k parity: s-1-P mod 2
#pragma unroll
        for (int k2 = 0; k2 < 16; ++k2) {
            const int k = 2 * k2 + kpar;
            if (k <= s - 1 && k <= 30) {
                const int slot = (8 + ((s + 15 - P - k) >> 1)) & 15;
                acc[slot] = ffma2(v, wr[k], acc[slot]);
            }
        }
        if (s == 31 && P == 0) {                     // first output o = l0
            stg_cs(op, acc[0]); acc[0] = bb; op += 2 * CW;
        }
    }
}

// Main slab (s >= 32, full 31-tap stencil). Slot depends only on s mod 32
// (PHASE + u), store condition/slot on the same; +32/+47 offsets keep all
// shifts of even non-negative values (=== mod 16 to the exact formulas).
template <int PHASE, int P, bool LAST>
__device__ __forceinline__ void main_slab(const u64* __restrict__ sl, int lane,
                                          const u64* __restrict__ wr,
                                          u64* __restrict__ acc, u64 bb,
                                          u64*& op)
{
#pragma unroll
    for (int u = 0; u < (LAST ? 15 : 16); ++u) {
        const int sp = PHASE + u;                    // s mod 32
        const u64 v = sl[u * 32 + lane];
        const int kpar = (sp + 1 + P) & 1;
#pragma unroll
        for (int k2 = 0; k2 < 16; ++k2) {
            const int k = 2 * k2 + kpar;
            if (k <= 30) {
                const int slot = (8 + ((sp + 47 - P - k) >> 1)) & 15;
                acc[slot] = ffma2(v, wr[k], acc[slot]);
            }
        }
        if (((sp + 17 - P) & 1) == 0) {              // s === 1+P (mod 2)
            const int st = (8 + ((sp + 17 - P) >> 1)) & 15;  // o = l0+s-31
            stg_cs(op, acc[st]); acc[st] = bb; op += 2 * CW;
        }
    }
}

__global__ void __launch_bounds__(TPB, 2)
dwconv_kernel(const float* __restrict__ x, const float* __restrict__ w,
              const float* __restrict__ bias, float* __restrict__ out)
{
    __shared__ __align__(16) u64 sbuf[4][3][16][32];    // 48 KB

    const int lane  = threadIdx.x & 31;
    const int warp  = threadIdx.x >> 5;
    const int group = warp >> 1;                        // 0..3
    const int par   = warp & 1;                         // output parity
    const int cpg   = blockIdx.y * 128 + group * 32 + lane;  // channel pair
    const int b     = blockIdx.z;
    const int l0    = blockIdx.x * RCH;

    Copier cc;
    {
        const int o16 = (lane & 15) * 16;
        const int r00 = par * 8 + (lane >> 4);          // first served row
        cc.xgo   = (const char*)x + (size_t)b * ((size_t)L_ * C_ * 4)
                 + (size_t)(blockIdx.y * 128 + group * 32) * 8 + o16;
        cc.sdst0 = (unsigned)__cvta_generic_to_shared(&sbuf[group][0][0][0])
                 + (unsigned)(r00 * 256 + o16);
        cc.q00   = l0 - 16 + r00;
    }

    const u64* wg = (const u64*)w;
    u64 wr[K_];
#pragma unroll
    for (int k = 0; k < K_; ++k) wr[k] = wg[k * CW + cpg];
    const u64 bb = ((const u64*)bias)[cpg];

    u64 acc[16];
#pragma unroll
    for (int i = 0; i < 16; ++i) acc[i] = bb;

    u64* op = (u64*)out + (size_t)b * ((size_t)L_ * CW)
            + (size_t)(l0 + par) * CW + cpg;

    cc.issue(0, 0); cc.issue(1, 1); cc.issue(2, 2);
    const u64* sw = &sbuf[group][0][0][0];

    // slab 0 (s = 0..15, ramp)
    cpwait<2>(); __syncthreads();
    if (par == 0) ramp_slab<0, 0>(sw, lane, wr, acc, bb, op);
    else          ramp_slab<0, 1>(sw, lane, wr, acc, bb, op);
    __syncthreads(); cc.issue(3, 0);

    // slab 1 (s = 16..31, ramp; first store at s=31)
    cpwait<2>(); __syncthreads();
    if (par == 0) ramp_slab<16, 0>(sw + 512, lane, wr, acc, bb, op);
    else          ramp_slab<16, 1>(sw + 512, lane, wr, acc, bb, op);
    __syncthreads(); cc.issue(4, 1);

    // slab 2 (s = 32..47, phase 0)
    cpwait<2>(); __syncthreads();
    if (par == 0) main_slab<0, 0, false>(sw + 1024, lane, wr, acc, bb, op);
    else          main_slab<0, 1, false>(sw + 1024, lane, wr, acc, bb, op);
    __syncthreads(); cc.issue(5, 2);

    // slab 3 (s = 48..63, phase 16)
    cpwait<2>(); __syncthreads();
    if (par == 0) main_slab<16, 0, false>(sw, lane, wr, acc, bb, op);
    else          main_slab<16, 1, false>(sw, lane, wr, acc, bb, op);
    __syncthreads(); cc.issue(6, 0);     // dummy commit

    // slab 4 (s = 64..79, phase 0)
    cpwait<2>(); __syncthreads();
    if (par == 0) main_slab<0, 0, false>(sw + 512, lane, wr, acc, bb, op);
    else          main_slab<0, 1, false>(sw + 512, lane, wr, acc, bb, op);
    __syncthreads(); cc.issue(7, 1);     // dummy commit

    // slab 5 (s = 80..94, phase 16, last)
    cpwait<2>(); __syncthreads();
    if (par == 0) main_slab<16, 0, true>(sw + 1024, lane, wr, acc, bb, op);
    else          main_slab<16, 1, true>(sw + 1024, lane, wr, acc, bb, op);
}

extern "C" void kernel_launch(void* const* d_in, const int* in_sizes, int n_in,
                              void* d_out, int out_size)
{
    const float* x    = (const float*)d_in[0];   // [B, L, C]
    const float* w    = (const float*)d_in[1];   // [K, C, 1]
    const float* bias = (const float*)d_in[2];   // [C]
    float*       out  = (float*)d_out;           // [B, L, C]

    dim3 grid(L_ / RCH, 2, B_);                  // (256, 2, 8) = 4096 CTAs
    dwconv_kernel<<<grid, TPB>>>(x, w, bias, out);
}